// round 10
// baseline (speedup 1.0000x reference)
#include <cuda_runtime.h>

// RoiPooling: torchvision roi_pool (max), OUT=7x7, SCALE=0.125
// input:  (4, 256, 100, 152) fp32 NCHW
// boxes:  (K, 5) fp32  [batch_idx, x1, y1, x2, y2] image coords
// output: (K, 256, 7, 7) fp32
//
// SEMANTIC (verified R4): XLA rewrites (x / 7.0f) -> x * (1/7.0f); bin sizes
// MUST be computed via __fmul_rn(x, 1.0f/7.0f) to bit-match the reference.
//
// Pipeline:
//  1) transpose NCHW -> NHWC scratch, float4 both directions
//  2) prep: per-(roi,bin) packed bounds (verified R6)
//  3) main: CTA=(roi, 128ch half), warp = ph band. Each row's columns are
//     walked ONCE; the <=1-column overlap between adjacent pw bins is
//     carried in a register (vprev), removing the column-redundancy of
//     the bin windows (reads x0.74).

static constexpr int N_   = 4;
static constexpr int C_   = 256;
static constexpr int H_   = 100;
static constexpr int W_   = 152;
static constexpr int HW_  = H_ * W_;
static constexpr int C4_  = C_ / 4;            // float4 per cell = 64
static constexpr int KMAX = 8192;

__device__ float        g_xT[N_ * HW_ * C_];   // NHWC scratch (62.3 MB)
__device__ unsigned int g_bounds[KMAX * 49];   // hs|he<<8|ws<<16|we<<24
__device__ int          g_baseT[KMAX];         // b * HW_ * C_

// ------------- 1) NCHW -> NHWC transpose, float4 in & out -------------
__global__ __launch_bounds__(256)
void transpose_nchw_nhwc(const float* __restrict__ x)
{
    __shared__ float tile[5][32][33];          // 21.1 KB, pitch 33
    const int b   = blockIdx.z;
    const int c0  = blockIdx.y * 32;
    const int hw0 = blockIdx.x * 160;          // 5 x 32 hw cells
    const int t   = threadIdx.x;

    const float* src = x + ((size_t)b * C_) * HW_;
    float*       dst = g_xT + (size_t)b * HW_ * C_;

    // load role: thread -> (channel row, float4 column)
    {
        const int cl  = t >> 3;                // 0..31
        const int hw8 = t & 7;                 // 0..7
        #pragma unroll
        for (int j = 0; j < 5; ++j) {
            const float4 v = *(const float4*)
                &src[(size_t)(c0 + cl) * HW_ + hw0 + j * 32 + hw8 * 4];
            tile[j][cl][hw8 * 4 + 0] = v.x;
            tile[j][cl][hw8 * 4 + 1] = v.y;
            tile[j][cl][hw8 * 4 + 2] = v.z;
            tile[j][cl][hw8 * 4 + 3] = v.w;
        }
    }
    __syncthreads();
    // store role: thread -> (hw row, float4 channel column)
    {
        const int hwl = t >> 3;                // 0..31
        const int c8  = t & 7;                 // 0..7
        #pragma unroll
        for (int j = 0; j < 5; ++j) {
            float4 w;
            w.x = tile[j][c8 * 4 + 0][hwl];
            w.y = tile[j][c8 * 4 + 1][hwl];
            w.z = tile[j][c8 * 4 + 2][hwl];
            w.w = tile[j][c8 * 4 + 3][hwl];
            *(float4*)&dst[(size_t)(hw0 + j * 32 + hwl) * C_ + c0 + c8 * 4] = w;
        }
    }
}

// ---------------- 2) per-(roi,bin) bounds prep ----------------
__global__ __launch_bounds__(256)
void roi_prep(const float* __restrict__ boxes, int kb_total)
{
    const int i = blockIdx.x * blockDim.x + threadIdx.x;
    if (i >= kb_total) return;
    const int bin = i % 49;
    const int k   = i / 49;
    const int pw  = bin % 7;
    const int ph  = bin / 7;

    const float* bx = boxes + (size_t)k * 5;
    const int b  = (int)bx[0];
    const int x1 = __float2int_rn(__fmul_rn(bx[1], 0.125f));
    const int y1 = __float2int_rn(__fmul_rn(bx[2], 0.125f));
    const int x2 = __float2int_rn(__fmul_rn(bx[3], 0.125f));
    const int y2 = __float2int_rn(__fmul_rn(bx[4], 0.125f));
    const int roi_w = max(x2 - x1 + 1, 1);
    const int roi_h = max(y2 - y1 + 1, 1);
    const float RCP7 = 1.0f / 7.0f;            // XLA reciprocal rewrite
    const float bin_h = __fmul_rn((float)roi_h, RCP7);
    const float bin_w = __fmul_rn((float)roi_w, RCP7);

    const int hs = min(max((int)floorf(__fmul_rn((float)ph,       bin_h)) + y1, 0), H_);
    const int he = min(max((int)ceilf (__fmul_rn((float)(ph + 1), bin_h)) + y1, 0), H_);
    const int ws = min(max((int)floorf(__fmul_rn((float)pw,       bin_w)) + x1, 0), W_);
    const int we = min(max((int)ceilf (__fmul_rn((float)(pw + 1), bin_w)) + x1, 0), W_);

    g_bounds[i] = (unsigned)hs | ((unsigned)he << 8)
                | ((unsigned)ws << 16) | ((unsigned)we << 24);
    if (bin == 0) g_baseT[k] = b * HW_ * C_;
}

// -------- 3) main gather: warp = ph band, single column walk per row ------
static constexpr int SPITCH = 33;              // float4 per bin row (pad)

__device__ __forceinline__ float4 f4max(float4 a, const float4 b) {
    a.x = fmaxf(a.x, b.x); a.y = fmaxf(a.y, b.y);
    a.z = fmaxf(a.z, b.z); a.w = fmaxf(a.w, b.w);
    return a;
}

__global__ __launch_bounds__(224)
void roi_pool_nhwc4(float* __restrict__ out)
{
    __shared__ float4 sres[49 * SPITCH];       // 25.9 KB

    const int k    = blockIdx.x >> 1;
    const int half = blockIdx.x & 1;
    const int c0q  = half * 32;
    const int ph   = threadIdx.x >> 5;         // warp = ph, 0..6
    const int lane = threadIdx.x & 31;

    const float4* srcq = (const float4*)g_xT;
    const int baseq = (g_baseT[k] >> 2) + c0q + lane;
    const unsigned int* bnd = g_bounds + k * 49 + ph * 7;

    const float NI = __int_as_float(0xff800000);

    int wsA[7], weA[7];
    #pragma unroll
    for (int pw = 0; pw < 7; ++pw) {
        const unsigned u = bnd[pw];            // same addr across warp
        wsA[pw] = (u >> 16) & 0xff;
        weA[pw] =  u >> 24;
    }
    const unsigned u0 = bnd[0];
    const int hs =  u0       & 0xff;
    const int he = (u0 >> 8) & 0xff;

    float4 acc[7];
    #pragma unroll
    for (int pw = 0; pw < 7; ++pw) acc[pw] = make_float4(NI, NI, NI, NI);

    for (int r = hs; r < he; ++r) {
        const int rowq = baseq + r * (W_ * C4_);
        int    cc = -1;                        // next unread column
        float4 vprev;                          // value at column cc-1
        #pragma unroll
        for (int pw = 0; pw < 7; ++pw) {
            const int s = wsA[pw], e = weA[pw];
            if (e > s) {
                float4 m;
                int c;
                if (s < cc) { m = vprev; c = cc; }       // reuse overlap col
                else { vprev = srcq[rowq + s * C4_]; m = vprev; c = s + 1; }
                for (; c < e; ++c) {
                    vprev = srcq[rowq + c * C4_];
                    m = f4max(m, vprev);
                }
                cc = e;
                acc[pw] = f4max(acc[pw], m);
            }
        }
    }

    #pragma unroll
    for (int pw = 0; pw < 7; ++pw) {
        const bool empty = (he <= hs) || (weA[pw] <= wsA[pw]);
        const float4 m = empty ? make_float4(0.f, 0.f, 0.f, 0.f) : acc[pw];
        sres[(ph * 7 + pw) * SPITCH + lane] = m;
    }
    __syncthreads();

    // coalesced write: out[k*12544 + (c0 + cloc)*49 + bin]
    const float* s = (const float*)sres;       // bin row = 132 floats
    float* dst = out + (size_t)k * (C_ * 49) + (size_t)(half * 128) * 49;
    for (int i = threadIdx.x; i < 128 * 49; i += 224) {   // 28 exact iters
        const int cloc = i / 49;
        const int bin  = i - cloc * 49;
        dst[i] = s[bin * (SPITCH * 4) + cloc];
    }
}

extern "C" void kernel_launch(void* const* d_in, const int* in_sizes, int n_in,
                              void* d_out, int out_size) {
    const float* x     = (const float*)d_in[0];
    const float* boxes = (const float*)d_in[1];
    float*       out   = (float*)d_out;
    const int K = in_sizes[1] / 5;               // boxes is (K, 5)

    dim3 tg(HW_ / 160, C_ / 32, N_);             // 95 x 8 x 4
    transpose_nchw_nhwc<<<tg, 256>>>(x);

    const int kb_total = K * 49;
    roi_prep<<<(kb_total + 255) / 256, 256>>>(boxes, kb_total);

    roi_pool_nhwc4<<<K * 2, 224>>>(out);
}

// round 11
// speedup vs baseline: 1.5026x; 1.5026x over previous
#include <cuda_runtime.h>

// RoiPooling: torchvision roi_pool (max), OUT=7x7, SCALE=0.125
// input:  (4, 256, 100, 152) fp32 NCHW
// boxes:  (K, 5) fp32  [batch_idx, x1, y1, x2, y2] image coords
// output: (K, 256, 7, 7) fp32
//
// SEMANTIC (verified R4): XLA rewrites (x / 7.0f) -> x * (1/7.0f); bin sizes
// MUST be computed via __fmul_rn(x, 1.0f/7.0f) to bit-match the reference.
//
// Pipeline:
//  1) transpose NCHW -> NHWC scratch (float4 both ways)
//  2) prep: per-(roi,bin) packed bounds (verified R6)
//  3) main: CTA=(roi, 128ch half). warp = pw COLUMN band, lane = 4 channels.
//     Each warp walks the ROI height once: per row it loads its band's
//     cells (independent float4s), reduces to a column-max, and folds into
//     7 per-ph accumulators (hs/he monotonic, warp-uniform checks).
//     -> row redundancy of bin windows eliminated, MLP preserved.

static constexpr int N_   = 4;
static constexpr int C_   = 256;
static constexpr int H_   = 100;
static constexpr int W_   = 152;
static constexpr int HW_  = H_ * W_;
static constexpr int C4_  = C_ / 4;            // float4 per cell = 64
static constexpr int KMAX = 8192;

__device__ float        g_xT[N_ * HW_ * C_];   // NHWC scratch (62.3 MB)
__device__ unsigned int g_bounds[KMAX * 49];   // hs|he<<8|ws<<16|we<<24
__device__ int          g_baseT[KMAX];         // b * HW_ * C_

// ------------- 1) NCHW -> NHWC transpose, float4 in & out -------------
__global__ __launch_bounds__(256)
void transpose_nchw_nhwc(const float* __restrict__ x)
{
    __shared__ float tile[5][32][33];          // 21.1 KB, pitch 33
    const int b   = blockIdx.z;
    const int c0  = blockIdx.y * 32;
    const int hw0 = blockIdx.x * 160;          // 5 x 32 hw cells
    const int t   = threadIdx.x;

    const float* src = x + ((size_t)b * C_) * HW_;
    float*       dst = g_xT + (size_t)b * HW_ * C_;

    {
        const int cl  = t >> 3;                // 0..31
        const int hw8 = t & 7;                 // 0..7
        #pragma unroll
        for (int j = 0; j < 5; ++j) {
            const float4 v = *(const float4*)
                &src[(size_t)(c0 + cl) * HW_ + hw0 + j * 32 + hw8 * 4];
            tile[j][cl][hw8 * 4 + 0] = v.x;
            tile[j][cl][hw8 * 4 + 1] = v.y;
            tile[j][cl][hw8 * 4 + 2] = v.z;
            tile[j][cl][hw8 * 4 + 3] = v.w;
        }
    }
    __syncthreads();
    {
        const int hwl = t >> 3;                // 0..31
        const int c8  = t & 7;                 // 0..7
        #pragma unroll
        for (int j = 0; j < 5; ++j) {
            float4 w;
            w.x = tile[j][c8 * 4 + 0][hwl];
            w.y = tile[j][c8 * 4 + 1][hwl];
            w.z = tile[j][c8 * 4 + 2][hwl];
            w.w = tile[j][c8 * 4 + 3][hwl];
            *(float4*)&dst[(size_t)(hw0 + j * 32 + hwl) * C_ + c0 + c8 * 4] = w;
        }
    }
}

// ---------------- 2) per-(roi,bin) bounds prep ----------------
__global__ __launch_bounds__(256)
void roi_prep(const float* __restrict__ boxes, int kb_total)
{
    const int i = blockIdx.x * blockDim.x + threadIdx.x;
    if (i >= kb_total) return;
    const int bin = i % 49;
    const int k   = i / 49;
    const int pw  = bin % 7;
    const int ph  = bin / 7;

    const float* bx = boxes + (size_t)k * 5;
    const int b  = (int)bx[0];
    const int x1 = __float2int_rn(__fmul_rn(bx[1], 0.125f));
    const int y1 = __float2int_rn(__fmul_rn(bx[2], 0.125f));
    const int x2 = __float2int_rn(__fmul_rn(bx[3], 0.125f));
    const int y2 = __float2int_rn(__fmul_rn(bx[4], 0.125f));
    const int roi_w = max(x2 - x1 + 1, 1);
    const int roi_h = max(y2 - y1 + 1, 1);
    const float RCP7 = 1.0f / 7.0f;            // XLA reciprocal rewrite
    const float bin_h = __fmul_rn((float)roi_h, RCP7);
    const float bin_w = __fmul_rn((float)roi_w, RCP7);

    const int hs = min(max((int)floorf(__fmul_rn((float)ph,       bin_h)) + y1, 0), H_);
    const int he = min(max((int)ceilf (__fmul_rn((float)(ph + 1), bin_h)) + y1, 0), H_);
    const int ws = min(max((int)floorf(__fmul_rn((float)pw,       bin_w)) + x1, 0), W_);
    const int we = min(max((int)ceilf (__fmul_rn((float)(pw + 1), bin_w)) + x1, 0), W_);

    g_bounds[i] = (unsigned)hs | ((unsigned)he << 8)
                | ((unsigned)ws << 16) | ((unsigned)we << 24);
    if (bin == 0) g_baseT[k] = b * HW_ * C_;
}

// -------- 3) main gather: warp = pw band, single pass over rows ----------
static constexpr int SPITCH = 33;              // float4 per bin row (pad)

__device__ __forceinline__ float4 f4max(float4 a, const float4 b) {
    a.x = fmaxf(a.x, b.x); a.y = fmaxf(a.y, b.y);
    a.z = fmaxf(a.z, b.z); a.w = fmaxf(a.w, b.w);
    return a;
}

__global__ __launch_bounds__(224)
void roi_pool_nhwc4(float* __restrict__ out)
{
    __shared__ float4 sres[49 * SPITCH];       // 25.9 KB

    const int k    = blockIdx.x >> 1;
    const int half = blockIdx.x & 1;
    const int c0q  = half * 32;
    const int pw   = threadIdx.x >> 5;         // warp = pw band, 0..6
    const int lane = threadIdx.x & 31;

    const float4* srcq = (const float4*)g_xT;
    const int baseq = (g_baseT[k] >> 2) + c0q + lane;
    const unsigned int* bnd = g_bounds + k * 49;

    const float NI = __int_as_float(0xff800000);

    // this warp's column band (pw); row bounds for all ph
    const unsigned upw = bnd[pw];
    const int ws = (upw >> 16) & 0xff;
    const int we =  upw >> 24;

    int hsA[7], heA[7];
    #pragma unroll
    for (int ph = 0; ph < 7; ++ph) {
        const unsigned u = bnd[ph * 7];        // hs/he depend only on ph
        hsA[ph] =  u       & 0xff;
        heA[ph] = (u >> 8) & 0xff;
    }

    float4 acc[7];
    #pragma unroll
    for (int ph = 0; ph < 7; ++ph) acc[ph] = make_float4(NI, NI, NI, NI);

    if (we > ws) {
        const int r0 = hsA[0];
        const int r1 = heA[6];
        for (int r = r0; r < r1; ++r) {
            const int rowq = baseq + r * (W_ * C4_);
            // column max over this band: independent LDG.128s
            float4 cm = srcq[rowq + ws * C4_];
            for (int cc = ws + 1; cc < we; ++cc)
                cm = f4max(cm, srcq[rowq + cc * C4_]);
            // fold into active ph bins (warp-uniform; <=2 taken)
            #pragma unroll
            for (int ph = 0; ph < 7; ++ph)
                if (r >= hsA[ph] && r < heA[ph])
                    acc[ph] = f4max(acc[ph], cm);
        }
    }

    #pragma unroll
    for (int ph = 0; ph < 7; ++ph) {
        const bool empty = (heA[ph] <= hsA[ph]) || (we <= ws);
        const float4 m = empty ? make_float4(0.f, 0.f, 0.f, 0.f) : acc[ph];
        sres[(ph * 7 + pw) * SPITCH + lane] = m;
    }
    __syncthreads();

    // coalesced write: out[k*12544 + (c0 + cloc)*49 + bin]
    const float* s = (const float*)sres;       // bin row = 132 floats
    float* dst = out + (size_t)k * (C_ * 49) + (size_t)(half * 128) * 49;
    for (int i = threadIdx.x; i < 128 * 49; i += 224) {   // 28 exact iters
        const int cloc = i / 49;
        const int bin  = i - cloc * 49;
        dst[i] = s[bin * (SPITCH * 4) + cloc];
    }
}

extern "C" void kernel_launch(void* const* d_in, const int* in_sizes, int n_in,
                              void* d_out, int out_size) {
    const float* x     = (const float*)d_in[0];
    const float* boxes = (const float*)d_in[1];
    float*       out   = (float*)d_out;
    const int K = in_sizes[1] / 5;               // boxes is (K, 5)

    dim3 tg(HW_ / 160, C_ / 32, N_);             // 95 x 8 x 4
    transpose_nchw_nhwc<<<tg, 256>>>(x);

    const int kb_total = K * 49;
    roi_prep<<<(kb_total + 255) / 256, 256>>>(boxes, kb_total);

    roi_pool_nhwc4<<<K * 2, 224>>>(out);
}

// round 12
// speedup vs baseline: 1.5352x; 1.0217x over previous
#include <cuda_runtime.h>

// RoiPooling: torchvision roi_pool (max), OUT=7x7, SCALE=0.125
// input:  (4, 256, 100, 152) fp32 NCHW
// boxes:  (K, 5) fp32  [batch_idx, x1, y1, x2, y2] image coords
// output: (K, 256, 7, 7) fp32
//
// SEMANTIC (verified R4): XLA rewrites (x / 7.0f) -> x * (1/7.0f); bin sizes
// MUST be computed via __fmul_rn(x, 1.0f/7.0f) to bit-match the reference.
//
// Pipeline (order: prep -> transpose -> main, so ncu -s5 captures MAIN):
//  1) prep: per-(roi,bin) packed bounds (verified R6)
//  2) transpose NCHW -> NHWC, 2 channel-groups x 5 hw-tiles per CTA
//  3) main (R9-exact, best known): CTA=(roi, 128ch half), 7 warps,
//     warp = ph row of 7 bins, lane = 4 channels, 2x2 unrolled float4.

static constexpr int N_   = 4;
static constexpr int C_   = 256;
static constexpr int H_   = 100;
static constexpr int W_   = 152;
static constexpr int HW_  = H_ * W_;
static constexpr int C4_  = C_ / 4;            // float4 per cell = 64
static constexpr int KMAX = 8192;

__device__ float        g_xT[N_ * HW_ * C_];   // NHWC scratch (62.3 MB)
__device__ unsigned int g_bounds[KMAX * 49];   // hs|he<<8|ws<<16|we<<24
__device__ int          g_baseT[KMAX];         // b * HW_ * C_

// ---------------- 1) per-(roi,bin) bounds prep ----------------
__global__ __launch_bounds__(256)
void roi_prep(const float* __restrict__ boxes, int kb_total)
{
    const int i = blockIdx.x * blockDim.x + threadIdx.x;
    if (i >= kb_total) return;
    const int bin = i % 49;
    const int k   = i / 49;
    const int pw  = bin % 7;
    const int ph  = bin / 7;

    const float* bx = boxes + (size_t)k * 5;
    const int b  = (int)bx[0];
    const int x1 = __float2int_rn(__fmul_rn(bx[1], 0.125f));
    const int y1 = __float2int_rn(__fmul_rn(bx[2], 0.125f));
    const int x2 = __float2int_rn(__fmul_rn(bx[3], 0.125f));
    const int y2 = __float2int_rn(__fmul_rn(bx[4], 0.125f));
    const int roi_w = max(x2 - x1 + 1, 1);
    const int roi_h = max(y2 - y1 + 1, 1);
    const float RCP7 = 1.0f / 7.0f;            // XLA reciprocal rewrite
    const float bin_h = __fmul_rn((float)roi_h, RCP7);
    const float bin_w = __fmul_rn((float)roi_w, RCP7);

    const int hs = min(max((int)floorf(__fmul_rn((float)ph,       bin_h)) + y1, 0), H_);
    const int he = min(max((int)ceilf (__fmul_rn((float)(ph + 1), bin_h)) + y1, 0), H_);
    const int ws = min(max((int)floorf(__fmul_rn((float)pw,       bin_w)) + x1, 0), W_);
    const int we = min(max((int)ceilf (__fmul_rn((float)(pw + 1), bin_w)) + x1, 0), W_);

    g_bounds[i] = (unsigned)hs | ((unsigned)he << 8)
                | ((unsigned)ws << 16) | ((unsigned)we << 24);
    if (bin == 0) g_baseT[k] = b * HW_ * C_;
}

// ------------- 2) NCHW -> NHWC transpose: 2 c-groups x 5 hw-tiles ----------
__global__ __launch_bounds__(256)
void transpose_nchw_nhwc(const float* __restrict__ x)
{
    __shared__ float tile[2][5][32][33];       // 42.2 KB
    const int b   = blockIdx.z;
    const int c0  = blockIdx.y * 64;           // 2 channel groups of 32
    const int hw0 = blockIdx.x * 160;          // 5 x 32 hw cells
    const int t   = threadIdx.x;

    const float* src = x + ((size_t)b * C_) * HW_;
    float*       dst = g_xT + (size_t)b * HW_ * C_;

    {
        const int cl  = t >> 3;                // 0..31
        const int hw8 = t & 7;                 // 0..7
        #pragma unroll
        for (int g = 0; g < 2; ++g)
            #pragma unroll
            for (int j = 0; j < 5; ++j) {      // 10 independent LDG.128
                const float4 v = *(const float4*)
                    &src[(size_t)(c0 + g * 32 + cl) * HW_ + hw0 + j * 32 + hw8 * 4];
                tile[g][j][cl][hw8 * 4 + 0] = v.x;
                tile[g][j][cl][hw8 * 4 + 1] = v.y;
                tile[g][j][cl][hw8 * 4 + 2] = v.z;
                tile[g][j][cl][hw8 * 4 + 3] = v.w;
            }
    }
    __syncthreads();
    {
        const int hwl = t >> 3;                // 0..31
        const int c8  = t & 7;                 // 0..7
        #pragma unroll
        for (int g = 0; g < 2; ++g)
            #pragma unroll
            for (int j = 0; j < 5; ++j) {
                float4 w;
                w.x = tile[g][j][c8 * 4 + 0][hwl];
                w.y = tile[g][j][c8 * 4 + 1][hwl];
                w.z = tile[g][j][c8 * 4 + 2][hwl];
                w.w = tile[g][j][c8 * 4 + 3][hwl];
                *(float4*)&dst[(size_t)(hw0 + j * 32 + hwl) * C_
                               + c0 + g * 32 + c8 * 4] = w;
            }
    }
}

// -------- 3) main gather (R9-exact): 7 warps, warp = bin row --------------
static constexpr int SPITCH = 33;              // float4 per bin row (pad)

__device__ __forceinline__ float4 f4max(float4 a, const float4 b) {
    a.x = fmaxf(a.x, b.x); a.y = fmaxf(a.y, b.y);
    a.z = fmaxf(a.z, b.z); a.w = fmaxf(a.w, b.w);
    return a;
}

__global__ __launch_bounds__(224)
void roi_pool_nhwc4(float* __restrict__ out)
{
    __shared__ float4 sres[49 * SPITCH];       // 25.9 KB

    const int k    = blockIdx.x >> 1;
    const int half = blockIdx.x & 1;
    const int c0q  = half * 32;
    const int wid  = threadIdx.x >> 5;         // 0..6
    const int lane = threadIdx.x & 31;

    const float4* srcq = (const float4*)g_xT;
    const int baseq = (g_baseT[k] >> 2) + c0q + lane;
    const unsigned int* bnd = g_bounds + k * 49;

    const float NI = __int_as_float(0xff800000);

    #pragma unroll
    for (int t = 0; t < 7; ++t) {              // exactly 7 bins per warp
        const int bin = wid * 7 + t;
        const unsigned w32 = bnd[bin];
        const int hs =  w32        & 0xff;
        const int he = (w32 >> 8)  & 0xff;
        const int ws = (w32 >> 16) & 0xff;
        const int we = (w32 >> 24) & 0xff;

        float4 m = make_float4(NI, NI, NI, NI);
        int r = hs;
        for (; r + 1 < he; r += 2) {
            const int r0 = baseq + r * (W_ * C4_);
            const int r1 = r0 + (W_ * C4_);
            int cc = ws;
            for (; cc + 1 < we; cc += 2) {     // 4 independent LDG.128
                m = f4max(m, srcq[r0 + cc * C4_]);
                m = f4max(m, srcq[r0 + (cc + 1) * C4_]);
                m = f4max(m, srcq[r1 + cc * C4_]);
                m = f4max(m, srcq[r1 + (cc + 1) * C4_]);
            }
            if (cc < we) {
                m = f4max(m, srcq[r0 + cc * C4_]);
                m = f4max(m, srcq[r1 + cc * C4_]);
            }
        }
        if (r < he) {
            const int r0 = baseq + r * (W_ * C4_);
            int cc = ws;
            for (; cc + 1 < we; cc += 2) {
                m = f4max(m, srcq[r0 + cc * C4_]);
                m = f4max(m, srcq[r0 + (cc + 1) * C4_]);
            }
            if (cc < we)
                m = f4max(m, srcq[r0 + cc * C4_]);
        }
        if ((he <= hs) || (we <= ws))
            m = make_float4(0.f, 0.f, 0.f, 0.f);
        sres[bin * SPITCH + lane] = m;
    }
    __syncthreads();

    // coalesced write: out[k*12544 + (c0 + cloc)*49 + bin]
    const float* s = (const float*)sres;       // bin row = 132 floats
    float* dst = out + (size_t)k * (C_ * 49) + (size_t)(half * 128) * 49;
    for (int i = threadIdx.x; i < 128 * 49; i += 224) {   // 28 exact iters
        const int cloc = i / 49;
        const int bin  = i - cloc * 49;
        dst[i] = s[bin * (SPITCH * 4) + cloc];
    }
}

extern "C" void kernel_launch(void* const* d_in, const int* in_sizes, int n_in,
                              void* d_out, int out_size) {
    const float* x     = (const float*)d_in[0];
    const float* boxes = (const float*)d_in[1];
    float*       out   = (float*)d_out;
    const int K = in_sizes[1] / 5;               // boxes is (K, 5)

    // prep FIRST so ncu (-s 5 -c 1, 3 launches/replay) captures the MAIN
    // kernel (6th launch) instead of the transpose.
    const int kb_total = K * 49;
    roi_prep<<<(kb_total + 255) / 256, 256>>>(boxes, kb_total);

    dim3 tg(HW_ / 160, C_ / 64, N_);             // 95 x 4 x 4
    transpose_nchw_nhwc<<<tg, 256>>>(x);

    roi_pool_nhwc4<<<K * 2, 224>>>(out);
}

// round 13
// speedup vs baseline: 1.5600x; 1.0161x over previous
#include <cuda_runtime.h>

// RoiPooling: torchvision roi_pool (max), OUT=7x7, SCALE=0.125
// input:  (4, 256, 100, 152) fp32 NCHW
// boxes:  (K, 5) fp32  [batch_idx, x1, y1, x2, y2] image coords
// output: (K, 256, 7, 7) fp32
//
// SEMANTIC (verified R4): XLA rewrites (x / 7.0f) -> x * (1/7.0f); bin sizes
// MUST be computed via __fmul_rn(x, 1.0f/7.0f) to bit-match the reference.
//
// Pipeline:
//  1) prep: per-(roi,bin) packed bounds (verified R6)
//  2) transpose NCHW -> NHWC (R9-exact version, 18.0us measured)
//  3) main: R9 gather + boundary-row caching: warp = pw COLUMN of bins,
//     loop ph ascending; the <=1-row overlap between consecutive ph bins is
//     reused from a register (band-max of last row), cutting ~30% of reads
//     while keeping all interior loads independent (R9's 2x2 unroll).

static constexpr int N_   = 4;
static constexpr int C_   = 256;
static constexpr int H_   = 100;
static constexpr int W_   = 152;
static constexpr int HW_  = H_ * W_;
static constexpr int C4_  = C_ / 4;            // float4 per cell = 64
static constexpr int KMAX = 8192;

__device__ float        g_xT[N_ * HW_ * C_];   // NHWC scratch (62.3 MB)
__device__ unsigned int g_bounds[KMAX * 49];   // hs|he<<8|ws<<16|we<<24
__device__ int          g_baseT[KMAX];         // b * HW_ * C_

// ---------------- 1) per-(roi,bin) bounds prep ----------------
__global__ __launch_bounds__(256)
void roi_prep(const float* __restrict__ boxes, int kb_total)
{
    const int i = blockIdx.x * blockDim.x + threadIdx.x;
    if (i >= kb_total) return;
    const int bin = i % 49;
    const int k   = i / 49;
    const int pw  = bin % 7;
    const int ph  = bin / 7;

    const float* bx = boxes + (size_t)k * 5;
    const int b  = (int)bx[0];
    const int x1 = __float2int_rn(__fmul_rn(bx[1], 0.125f));
    const int y1 = __float2int_rn(__fmul_rn(bx[2], 0.125f));
    const int x2 = __float2int_rn(__fmul_rn(bx[3], 0.125f));
    const int y2 = __float2int_rn(__fmul_rn(bx[4], 0.125f));
    const int roi_w = max(x2 - x1 + 1, 1);
    const int roi_h = max(y2 - y1 + 1, 1);
    const float RCP7 = 1.0f / 7.0f;            // XLA reciprocal rewrite
    const float bin_h = __fmul_rn((float)roi_h, RCP7);
    const float bin_w = __fmul_rn((float)roi_w, RCP7);

    const int hs = min(max((int)floorf(__fmul_rn((float)ph,       bin_h)) + y1, 0), H_);
    const int he = min(max((int)ceilf (__fmul_rn((float)(ph + 1), bin_h)) + y1, 0), H_);
    const int ws = min(max((int)floorf(__fmul_rn((float)pw,       bin_w)) + x1, 0), W_);
    const int we = min(max((int)ceilf (__fmul_rn((float)(pw + 1), bin_w)) + x1, 0), W_);

    g_bounds[i] = (unsigned)hs | ((unsigned)he << 8)
                | ((unsigned)ws << 16) | ((unsigned)we << 24);
    if (bin == 0) g_baseT[k] = b * HW_ * C_;
}

// ------------- 2) NCHW -> NHWC transpose (R9-exact, 18.0us) -------------
__global__ __launch_bounds__(256)
void transpose_nchw_nhwc(const float* __restrict__ x)
{
    __shared__ float tile[5][32][33];          // 21.1 KB
    const int b   = blockIdx.z;
    const int c0  = blockIdx.y * 32;
    const int hw0 = blockIdx.x * 160;          // 5 x 32 hw cells
    const int tx  = threadIdx.x & 31;
    const int ty4 = threadIdx.x >> 5;          // 0..7

    const float* src = x + ((size_t)b * C_) * HW_;
    float*       dst = g_xT + (size_t)b * HW_ * C_;

    #pragma unroll
    for (int j = 0; j < 5; ++j)
        #pragma unroll
        for (int i = 0; i < 4; ++i) {
            const int c = c0 + ty4 * 4 + i;
            tile[j][ty4 * 4 + i][tx] = src[(size_t)c * HW_ + hw0 + j * 32 + tx];
        }
    __syncthreads();
    #pragma unroll
    for (int j = 0; j < 5; ++j)
        #pragma unroll
        for (int i = 0; i < 4; ++i) {
            const int hw = hw0 + j * 32 + ty4 * 4 + i;
            dst[(size_t)hw * C_ + c0 + tx] = tile[j][tx][ty4 * 4 + i];
        }
}

// ------ 3) main gather: warp = pw column, boundary-row register cache ------
static constexpr int SPITCH = 33;              // float4 per bin row (pad)

__device__ __forceinline__ float4 f4max(float4 a, const float4 b) {
    a.x = fmaxf(a.x, b.x); a.y = fmaxf(a.y, b.y);
    a.z = fmaxf(a.z, b.z); a.w = fmaxf(a.w, b.w);
    return a;
}

__global__ __launch_bounds__(224)
void roi_pool_nhwc4(float* __restrict__ out)
{
    __shared__ float4 sres[49 * SPITCH];       // 25.9 KB

    const int k    = blockIdx.x >> 1;
    const int half = blockIdx.x & 1;
    const int c0q  = half * 32;
    const int pw   = threadIdx.x >> 5;         // warp = pw column, 0..6
    const int lane = threadIdx.x & 31;

    const float4* srcq = (const float4*)g_xT;
    const int baseq = (g_baseT[k] >> 2) + c0q + lane;
    const unsigned int* bnd = g_bounds + k * 49;

    const float NI = __int_as_float(0xff800000);

    // this warp's column band (same ws/we for all ph)
    const unsigned u0 = bnd[pw];
    const int ws = (u0 >> 16) & 0xff;
    const int we =  u0 >> 24;
    const bool bandOk = (we > ws);

    int    prevRow = -1000;                    // row index of cached band-max
    float4 prevMax;

    #pragma unroll
    for (int ph = 0; ph < 7; ++ph) {
        const unsigned u = bnd[ph * 7 + pw];
        const int hs =  u       & 0xff;
        const int he = (u >> 8) & 0xff;

        float4 m = make_float4(NI, NI, NI, NI);
        if (bandOk && he > hs) {
            int r = hs;
            if (prevRow == hs) { m = prevMax; r = hs + 1; }   // reuse overlap row

            if (r < he) {
                // middle rows [r, he-1): R9-style 2-row x 2-col unroll
                for (; r + 2 < he; r += 2) {
                    const int r0 = baseq + r * (W_ * C4_);
                    const int r1 = r0 + (W_ * C4_);
                    int cc = ws;
                    for (; cc + 1 < we; cc += 2) {       // 4 indep LDG.128
                        m = f4max(m, srcq[r0 + cc * C4_]);
                        m = f4max(m, srcq[r0 + (cc + 1) * C4_]);
                        m = f4max(m, srcq[r1 + cc * C4_]);
                        m = f4max(m, srcq[r1 + (cc + 1) * C4_]);
                    }
                    if (cc < we) {
                        m = f4max(m, srcq[r0 + cc * C4_]);
                        m = f4max(m, srcq[r1 + cc * C4_]);
                    }
                }
                if (r < he - 1) {                        // one leftover middle row
                    const int r0 = baseq + r * (W_ * C4_);
                    int cc = ws;
                    for (; cc + 1 < we; cc += 2) {
                        m = f4max(m, srcq[r0 + cc * C4_]);
                        m = f4max(m, srcq[r0 + (cc + 1) * C4_]);
                    }
                    if (cc < we)
                        m = f4max(m, srcq[r0 + cc * C4_]);
                    ++r;
                }
                // last row (he-1): keep its band-max for the next ph bin
                {
                    const int r0 = baseq + (he - 1) * (W_ * C4_);
                    float4 lm = srcq[r0 + ws * C4_];
                    int cc = ws + 1;
                    for (; cc + 1 < we; cc += 2) {
                        lm = f4max(lm, srcq[r0 + cc * C4_]);
                        lm = f4max(lm, srcq[r0 + (cc + 1) * C4_]);
                    }
                    if (cc < we)
                        lm = f4max(lm, srcq[r0 + cc * C4_]);
                    m = f4max(m, lm);
                    prevMax = lm;
                    prevRow = he - 1;
                }
            }
            // if reuse covered the single row (he==hs+1): prevRow==hs==he-1 ok
        }

        const bool empty = (he <= hs) || !bandOk;
        sres[(ph * 7 + pw) * SPITCH + lane] =
            empty ? make_float4(0.f, 0.f, 0.f, 0.f) : m;
    }
    __syncthreads();

    // coalesced write: out[k*12544 + (c0 + cloc)*49 + bin]
    const float* s = (const float*)sres;       // bin row = 132 floats
    float* dst = out + (size_t)k * (C_ * 49) + (size_t)(half * 128) * 49;
    for (int i = threadIdx.x; i < 128 * 49; i += 224) {   // 28 exact iters
        const int cloc = i / 49;
        const int bin  = i - cloc * 49;
        dst[i] = s[bin * (SPITCH * 4) + cloc];
    }
}

extern "C" void kernel_launch(void* const* d_in, const int* in_sizes, int n_in,
                              void* d_out, int out_size) {
    const float* x     = (const float*)d_in[0];
    const float* boxes = (const float*)d_in[1];
    float*       out   = (float*)d_out;
    const int K = in_sizes[1] / 5;               // boxes is (K, 5)

    const int kb_total = K * 49;
    roi_prep<<<(kb_total + 255) / 256, 256>>>(boxes, kb_total);

    dim3 tg(HW_ / 160, C_ / 32, N_);             // 95 x 8 x 4
    transpose_nchw_nhwc<<<tg, 256>>>(x);

    roi_pool_nhwc4<<<K * 2, 224>>>(out);
}

// round 14
// speedup vs baseline: 1.6285x; 1.0439x over previous
#include <cuda_runtime.h>

// RoiPooling: torchvision roi_pool (max), OUT=7x7, SCALE=0.125
// input:  (4, 256, 100, 152) fp32 NCHW
// boxes:  (K, 5) fp32  [batch_idx, x1, y1, x2, y2] image coords
// output: (K, 256, 7, 7) fp32
//
// SEMANTIC (verified R4): XLA rewrites (x / 7.0f) -> x * (1/7.0f); bin sizes
// MUST be computed via __fmul_rn(x, 1.0f/7.0f) to bit-match the reference.
//
// Pipeline (2 launches):
//  1) fused kernel: blocks [0,3040) transpose NCHW->NHWC (R9-exact body);
//     blocks [3040,3432) compute per-(roi,bin) packed bounds (prep).
//     Prep is latency-bound and tiny -> hidden inside the DRAM-bound
//     transpose instead of a serialized 4.5us launch.
//  2) main gather (R9-exact, best measured): CTA=(roi, 128ch half),
//     7 warps, warp = ph row of 7 bins, lane = 4 channels, 2x2 float4.

static constexpr int N_   = 4;
static constexpr int C_   = 256;
static constexpr int H_   = 100;
static constexpr int W_   = 152;
static constexpr int HW_  = H_ * W_;
static constexpr int C4_  = C_ / 4;            // float4 per cell = 64
static constexpr int KMAX = 8192;

static constexpr int TBLK = (HW_ / 160) * (C_ / 32) * N_;   // 3040 transpose blocks

__device__ float        g_xT[N_ * HW_ * C_];   // NHWC scratch (62.3 MB)
__device__ unsigned int g_bounds[KMAX * 49];   // hs|he<<8|ws<<16|we<<24
__device__ int          g_baseT[KMAX];         // b * HW_ * C_

// ---------- 1) fused transpose (R9-exact body) + bounds prep ----------
__global__ __launch_bounds__(256)
void transpose_and_prep(const float* __restrict__ x,
                        const float* __restrict__ boxes,
                        int kb_total)
{
    const int bx = blockIdx.x;

    if (bx < TBLK) {
        // ---- transpose role ----
        __shared__ float tile[5][32][33];      // 21.1 KB
        const int b   = bx / 760;              // 95*8 = 760 blocks per batch
        const int rem = bx - b * 760;
        const int c0  = (rem / 95) * 32;
        const int hw0 = (rem % 95) * 160;      // 5 x 32 hw cells
        const int tx  = threadIdx.x & 31;
        const int ty4 = threadIdx.x >> 5;      // 0..7

        const float* src = x + ((size_t)b * C_) * HW_;
        float*       dst = g_xT + (size_t)b * HW_ * C_;

        #pragma unroll
        for (int j = 0; j < 5; ++j)
            #pragma unroll
            for (int i = 0; i < 4; ++i) {
                const int c = c0 + ty4 * 4 + i;
                tile[j][ty4 * 4 + i][tx] = src[(size_t)c * HW_ + hw0 + j * 32 + tx];
            }
        __syncthreads();
        #pragma unroll
        for (int j = 0; j < 5; ++j)
            #pragma unroll
            for (int i = 0; i < 4; ++i) {
                const int hw = hw0 + j * 32 + ty4 * 4 + i;
                dst[(size_t)hw * C_ + c0 + tx] = tile[j][tx][ty4 * 4 + i];
            }
    } else {
        // ---- prep role: per-(roi,bin) packed bounds ----
        const int i = (bx - TBLK) * 256 + threadIdx.x;
        if (i >= kb_total) return;
        const int bin = i % 49;
        const int k   = i / 49;
        const int pw  = bin % 7;
        const int ph  = bin / 7;

        const float* bxp = boxes + (size_t)k * 5;
        const int b  = (int)bxp[0];
        const int x1 = __float2int_rn(__fmul_rn(bxp[1], 0.125f));
        const int y1 = __float2int_rn(__fmul_rn(bxp[2], 0.125f));
        const int x2 = __float2int_rn(__fmul_rn(bxp[3], 0.125f));
        const int y2 = __float2int_rn(__fmul_rn(bxp[4], 0.125f));
        const int roi_w = max(x2 - x1 + 1, 1);
        const int roi_h = max(y2 - y1 + 1, 1);
        const float RCP7 = 1.0f / 7.0f;        // XLA reciprocal rewrite
        const float bin_h = __fmul_rn((float)roi_h, RCP7);
        const float bin_w = __fmul_rn((float)roi_w, RCP7);

        const int hs = min(max((int)floorf(__fmul_rn((float)ph,       bin_h)) + y1, 0), H_);
        const int he = min(max((int)ceilf (__fmul_rn((float)(ph + 1), bin_h)) + y1, 0), H_);
        const int ws = min(max((int)floorf(__fmul_rn((float)pw,       bin_w)) + x1, 0), W_);
        const int we = min(max((int)ceilf (__fmul_rn((float)(pw + 1), bin_w)) + x1, 0), W_);

        g_bounds[i] = (unsigned)hs | ((unsigned)he << 8)
                    | ((unsigned)ws << 16) | ((unsigned)we << 24);
        if (bin == 0) g_baseT[k] = b * HW_ * C_;
    }
}

// -------- 2) main gather (R9-exact): 7 warps, warp = bin row --------------
static constexpr int SPITCH = 33;              // float4 per bin row (pad)

__device__ __forceinline__ float4 f4max(float4 a, const float4 b) {
    a.x = fmaxf(a.x, b.x); a.y = fmaxf(a.y, b.y);
    a.z = fmaxf(a.z, b.z); a.w = fmaxf(a.w, b.w);
    return a;
}

__global__ __launch_bounds__(224)
void roi_pool_nhwc4(float* __restrict__ out)
{
    __shared__ float4 sres[49 * SPITCH];       // 25.9 KB

    const int k    = blockIdx.x >> 1;
    const int half = blockIdx.x & 1;
    const int c0q  = half * 32;
    const int wid  = threadIdx.x >> 5;         // 0..6
    const int lane = threadIdx.x & 31;

    const float4* srcq = (const float4*)g_xT;
    const int baseq = (g_baseT[k] >> 2) + c0q + lane;
    const unsigned int* bnd = g_bounds + k * 49;

    const float NI = __int_as_float(0xff800000);

    #pragma unroll
    for (int t = 0; t < 7; ++t) {              // exactly 7 bins per warp
        const int bin = wid * 7 + t;
        const unsigned w32 = bnd[bin];
        const int hs =  w32        & 0xff;
        const int he = (w32 >> 8)  & 0xff;
        const int ws = (w32 >> 16) & 0xff;
        const int we = (w32 >> 24) & 0xff;

        float4 m = make_float4(NI, NI, NI, NI);
        int r = hs;
        for (; r + 1 < he; r += 2) {
            const int r0 = baseq + r * (W_ * C4_);
            const int r1 = r0 + (W_ * C4_);
            int cc = ws;
            for (; cc + 1 < we; cc += 2) {     // 4 independent LDG.128
                m = f4max(m, srcq[r0 + cc * C4_]);
                m = f4max(m, srcq[r0 + (cc + 1) * C4_]);
                m = f4max(m, srcq[r1 + cc * C4_]);
                m = f4max(m, srcq[r1 + (cc + 1) * C4_]);
            }
            if (cc < we) {
                m = f4max(m, srcq[r0 + cc * C4_]);
                m = f4max(m, srcq[r1 + cc * C4_]);
            }
        }
        if (r < he) {
            const int r0 = baseq + r * (W_ * C4_);
            int cc = ws;
            for (; cc + 1 < we; cc += 2) {
                m = f4max(m, srcq[r0 + cc * C4_]);
                m = f4max(m, srcq[r0 + (cc + 1) * C4_]);
            }
            if (cc < we)
                m = f4max(m, srcq[r0 + cc * C4_]);
        }
        if ((he <= hs) || (we <= ws))
            m = make_float4(0.f, 0.f, 0.f, 0.f);
        sres[bin * SPITCH + lane] = m;
    }
    __syncthreads();

    // coalesced write: out[k*12544 + (c0 + cloc)*49 + bin]
    const float* s = (const float*)sres;       // bin row = 132 floats
    float* dst = out + (size_t)k * (C_ * 49) + (size_t)(half * 128) * 49;
    for (int i = threadIdx.x; i < 128 * 49; i += 224) {   // 28 exact iters
        const int cloc = i / 49;
        const int bin  = i - cloc * 49;
        dst[i] = s[bin * (SPITCH * 4) + cloc];
    }
}

extern "C" void kernel_launch(void* const* d_in, const int* in_sizes, int n_in,
                              void* d_out, int out_size) {
    const float* x     = (const float*)d_in[0];
    const float* boxes = (const float*)d_in[1];
    float*       out   = (float*)d_out;
    const int K = in_sizes[1] / 5;               // boxes is (K, 5)

    const int kb_total   = K * 49;
    const int prep_blocks = (kb_total + 255) / 256;
    transpose_and_prep<<<TBLK + prep_blocks, 256>>>(x, boxes, kb_total);

    roi_pool_nhwc4<<<K * 2, 224>>>(out);
}